// round 6
// baseline (speedup 1.0000x reference)
#include <cuda_runtime.h>
#include <cstdint>
#include <math.h>

// Problem constants
#define K_DIM 13
#define N_DIM 4096
#define IK    416                 // I*K
#define ROW_FLOATS 13312          // one n's mask slab (floats)
#define PAIR_FLOATS 26624         // two n's
#define PAIR_BYTES  106496
#define PAIR_CHUNKS 6656          // PAIR_BYTES / 16
#define G_FLOATS    (2 * IK)      // g for two n's = 832 floats
#define THREADS 1024
#define GRID    152
#define NPAIRS  2048

// smem: 2 mask stages (2*106496 B) + 2 g stages (2*3328 B) = 219648 B
#define SMEM_TOTAL (2 * PAIR_BYTES + 2 * G_FLOATS * 4)

__device__ __forceinline__ void cp16(uint32_t dst, const void* src) {
    asm volatile("cp.async.cg.shared.global [%0], [%1], 16;"
                 :: "r"(dst), "l"(src) : "memory");
}

extern __shared__ __align__(16) float smem[];

__global__ void __launch_bounds__(THREADS, 1) plaq_kernel(
    const float* __restrict__ x,       // (I, N)
    const float* __restrict__ W,       // (O, I, K)
    const float* __restrict__ b,       // (O,)
    const float* __restrict__ mask,    // (N, O, I, K)
    const int*   __restrict__ shifts,  // (N, K)
    float*       __restrict__ out)     // (O, N)
{
    float* msh = smem;                       // 2 x PAIR_FLOATS
    float* gsh = smem + 2 * PAIR_FLOATS;     // 2 x G_FLOATS

    const int tid  = threadIdx.x;
    const int warp = tid >> 5;   // warp == o
    const int lane = tid & 31;

    // Hoist this warp's W row into registers (float4 chunks)
    float4 wf[4];
    {
        const float4* W4 = (const float4*)(W + warp * IK);
        #pragma unroll
        for (int j = 0; j < 3; ++j) wf[j] = W4[j * 32 + lane];
        wf[3] = (lane < 8) ? W4[96 + lane] : make_float4(0.f, 0.f, 0.f, 0.f);
    }
    const float bias = b[warp];
    const float e_const = 2.718281828459045f;
    const float scale = (2.0f + 2.0f * e_const) / (e_const - 1.0f);

    // Gather coordinates: threads 0..831 each own one (nl, e)
    const bool gact = (tid < 2 * IK);
    const int  nl   = tid / IK;               // which n of the pair
    const int  ge   = tid - nl * IK;
    const int  gi   = ge / K_DIM;
    const int  gk   = ge - gi * K_DIM;

    const int bid  = blockIdx.x;
    const int pcnt = (NPAIRS - bid + GRID - 1) / GRID;   // 13 or 14 pairs

    const uint32_t msh_addr = (uint32_t)__cvta_generic_to_shared(msh);

    // ---- Prologue: fill stage 0 with pair 0, gather g[0]
    {
        const int n0 = 2 * bid;
        const char* src = (const char*)(mask + (size_t)n0 * ROW_FLOATS);
        #pragma unroll
        for (int k = 0; k < 6; ++k) {
            const int c = tid + k * 1024;
            cp16(msh_addr + c * 16, src + (size_t)c * 16);
        }
        if (tid < 512) {
            const int c = tid + 6144;
            cp16(msh_addr + c * 16, src + (size_t)c * 16);
        }
        asm volatile("cp.async.commit_group;" ::: "memory");

        if (gact) {
            const int n = n0 + nl;
            gsh[nl * IK + ge] = x[gi * N_DIM + shifts[n * K_DIM + gk]];
        }
    }

    // ---- Main loop over pairs
    for (int it = 0; it < pcnt; ++it) {
        const int s  = it & 1;
        const int n0 = 2 * (bid + it * GRID);

        // 1. Prefetch next pair's gather into a register (hides shifts->x chain)
        const int  itn = it + 1;
        const bool hasnext = (itn < pcnt);
        const int  pn = bid + itn * GRID;
        float gv = 0.0f;
        if (gact && hasnext)
            gv = x[gi * N_DIM + shifts[(2 * pn + nl) * K_DIM + gk]];

        // 2. Wait for current stage's copy
        asm volatile("cp.async.wait_group 0;" ::: "memory");
        // 3. Barrier: stage s visible; everyone done with stage s^1 and gsh[s^1]
        __syncthreads();

        // 4. Issue refill of stage s^1 with pair it+1 (overlaps the consume below)
        if (hasnext) {
            const char* src = (const char*)(mask + (size_t)(2 * pn) * ROW_FLOATS);
            const uint32_t dst = msh_addr + (uint32_t)((s ^ 1) * PAIR_BYTES);
            #pragma unroll
            for (int k = 0; k < 6; ++k) {
                const int c = tid + k * 1024;
                cp16(dst + c * 16, src + (size_t)c * 16);
            }
            if (tid < 512) {
                const int c = tid + 6144;
                cp16(dst + c * 16, src + (size_t)c * 16);
            }
        }
        asm volatile("cp.async.commit_group;" ::: "memory");

        // 5. Consume both n's of the pair (conflict-free LDS.128)
        const float4* m0 = (const float4*)(msh + s * PAIR_FLOATS + warp * IK);
        const float4* m1 = (const float4*)(msh + s * PAIR_FLOATS + ROW_FLOATS + warp * IK);
        const float4* g0 = (const float4*)(gsh + s * G_FLOATS);
        const float4* g1 = (const float4*)(gsh + s * G_FLOATS + IK);

        float s0 = 0.0f, s1 = 0.0f;
        #pragma unroll
        for (int j = 0; j < 3; ++j) {
            const int c = j * 32 + lane;
            const float4 w  = wf[j];
            const float4 a0 = m0[c];
            const float4 ga = g0[c];
            s0 += a0.x*w.x*ga.x + a0.y*w.y*ga.y + a0.z*w.z*ga.z + a0.w*w.w*ga.w;
            const float4 a1 = m1[c];
            const float4 gb = g1[c];
            s1 += a1.x*w.x*gb.x + a1.y*w.y*gb.y + a1.z*w.z*gb.z + a1.w*w.w*gb.w;
        }
        if (lane < 8) {
            const int c = 96 + lane;
            const float4 w  = wf[3];
            const float4 a0 = m0[c];
            const float4 ga = g0[c];
            s0 += a0.x*w.x*ga.x + a0.y*w.y*ga.y + a0.z*w.z*ga.z + a0.w*w.w*ga.w;
            const float4 a1 = m1[c];
            const float4 gb = g1[c];
            s1 += a1.x*w.x*gb.x + a1.y*w.y*gb.y + a1.z*w.z*gb.z + a1.w*w.w*gb.w;
        }

        #pragma unroll
        for (int off = 16; off > 0; off >>= 1) {
            s0 += __shfl_xor_sync(0xffffffffu, s0, off);
            s1 += __shfl_xor_sync(0xffffffffu, s1, off);
        }

        if (lane == 0) {
            const float y0 = s0 + bias;
            const float y1 = s1 + bias;
            out[warp * N_DIM + n0]     = (1.0f / (1.0f + __expf(-y0)) - 0.5f) * scale;
            out[warp * N_DIM + n0 + 1] = (1.0f / (1.0f + __expf(-y1)) - 0.5f) * scale;
        }

        // 6. Commit the prefetched gather for it+1 (readers only after next sync)
        if (gact && hasnext)
            gsh[(s ^ 1) * G_FLOATS + nl * IK + ge] = gv;
    }
}

extern "C" void kernel_launch(void* const* d_in, const int* in_sizes, int n_in,
                              void* d_out, int out_size) {
    const float* x      = (const float*)d_in[0];
    const float* Wconv  = (const float*)d_in[1];
    const float* bconv  = (const float*)d_in[2];
    const float* mask   = (const float*)d_in[3];
    const int*   shifts = (const int*)d_in[4];
    float* out          = (float*)d_out;

    cudaFuncSetAttribute(plaq_kernel,
                         cudaFuncAttributeMaxDynamicSharedMemorySize, SMEM_TOTAL);
    plaq_kernel<<<GRID, THREADS, SMEM_TOTAL>>>(x, Wconv, bconv, mask, shifts, out);
}

// round 7
// speedup vs baseline: 1.0786x; 1.0786x over previous
#include <cuda_runtime.h>
#include <math.h>

// Problem constants
#define O_DIM 32
#define I_DIM 32
#define K_DIM 13
#define N_DIM 4096
#define IK    (I_DIM * K_DIM)    // 416
#define WSIZE (O_DIM * IK)       // 13312 floats = 53 KB

#define THREADS 1024
#define BLOCKS  304              // 152 SMs * 2 resident blocks

__global__ void __launch_bounds__(THREADS, 2) plaq_kernel(
    const float* __restrict__ x,       // (I, N)
    const float* __restrict__ W,       // (O, I, K)
    const float* __restrict__ b,       // (O,)
    const float* __restrict__ mask,    // (N, O, I, K)
    const int*   __restrict__ shifts,  // (N, K)
    float*       __restrict__ out)     // (O, N)
{
    __shared__ float Wsh[WSIZE];
    __shared__ float gsh[2][IK];

    const int tid  = threadIdx.x;
    const int warp = tid >> 5;   // warp == o
    const int lane = tid & 31;

    // Load W once per block
    #pragma unroll
    for (int e = tid; e < WSIZE; e += THREADS)
        Wsh[e] = W[e];

    // Gather coordinates (threads 0..415)
    const bool gact = (tid < IK);
    const int  gi   = tid / K_DIM;
    const int  gk   = tid - gi * K_DIM;

    // Prime gsh[0] with the first n's gather
    int n = blockIdx.x;
    if (gact)
        gsh[0][tid] = x[gi * N_DIM + shifts[n * K_DIM + gk]];
    __syncthreads();

    const float bias = b[warp];
    const float e_const = 2.718281828459045f;
    const float scale = (2.0f + 2.0f * e_const) / (e_const - 1.0f);

    int p = 0;
    for (; n < N_DIM; n += BLOCKS) {
        // ---- Prefetch next n's gather into a register (independent of dot below,
        //      so it issues first and its L2 chain hides under mask streaming)
        const int  nn = n + BLOCKS;
        const bool pf = gact && (nn < N_DIM);
        float gv = 0.0f;
        if (pf)
            gv = x[gi * N_DIM + shifts[nn * K_DIM + gk]];

        // ---- Dot: 13 coalesced scalar LDGs per warp (R1-proven pattern)
        const float* __restrict__ mrow = mask + ((size_t)n * O_DIM + warp) * IK;
        const float* __restrict__ wrow = Wsh + warp * IK;
        const float* __restrict__ grow = gsh[p];

        float sum = 0.0f;
        #pragma unroll
        for (int j = 0; j < K_DIM; ++j) {
            const int e = j * 32 + lane;     // 13*32 == 416 exactly
            sum += mrow[e] * wrow[e] * grow[e];
        }

        // ---- Warp reduction
        #pragma unroll
        for (int off = 16; off > 0; off >>= 1)
            sum += __shfl_xor_sync(0xffffffffu, sum, off);

        if (lane == 0) {
            const float y   = sum + bias;
            const float sig = 1.0f / (1.0f + __expf(-y));
            out[warp * N_DIM + n] = (sig - 0.5f) * scale;
        }

        // ---- Commit prefetched gather to the alternate buffer; single barrier
        if (pf) gsh[p ^ 1][tid] = gv;
        __syncthreads();
        p ^= 1;
    }
}

extern "C" void kernel_launch(void* const* d_in, const int* in_sizes, int n_in,
                              void* d_out, int out_size) {
    const float* x      = (const float*)d_in[0];
    const float* Wconv  = (const float*)d_in[1];
    const float* bconv  = (const float*)d_in[2];
    const float* mask   = (const float*)d_in[3];
    const int*   shifts = (const int*)d_in[4];
    float* out          = (float*)d_out;

    plaq_kernel<<<BLOCKS, THREADS>>>(x, Wconv, bconv, mask, shifts, out);
}

// round 8
// speedup vs baseline: 1.2224x; 1.1333x over previous
#include <cuda_runtime.h>
#include <math.h>

// Problem constants
#define O_DIM 32
#define I_DIM 32
#define K_DIM 13
#define N_DIM 4096
#define IK    (I_DIM * K_DIM)    // 416
#define WSIZE (O_DIM * IK)       // 13312 floats = 53 KB

#define THREADS 1024
#define BLOCKS  304              // 152 SMs * 2 resident blocks

// Transposed x: xT[n][i] = x[i][n]  (4096 x 32 floats = 512 KB, L2-resident)
__device__ float xT[N_DIM * I_DIM];

// ---------------------------------------------------------------------------
// Kernel A: tiled transpose of x (32 x 4096) -> xT (4096 x 32)
// ---------------------------------------------------------------------------
__global__ void __launch_bounds__(1024) transpose_kernel(const float* __restrict__ x)
{
    __shared__ float tile[32][33];
    const int tx = threadIdx.x;        // 0..31
    const int ty = threadIdx.y;        // 0..31
    const int n0 = blockIdx.x * 32;

    // Coalesced read: row ty of x, columns n0+tx
    tile[ty][tx] = x[ty * N_DIM + n0 + tx];
    __syncthreads();
    // Coalesced write: row (n0+ty) of xT, columns tx
    xT[(n0 + ty) * I_DIM + tx] = tile[tx][ty];
}

// ---------------------------------------------------------------------------
// Kernel B: R1 structure, warp == o, gather via xT rows (1 line per k)
// ---------------------------------------------------------------------------
__global__ void __launch_bounds__(THREADS, 2) plaq_kernel(
    const float* __restrict__ W,       // (O, I, K)
    const float* __restrict__ b,       // (O,)
    const float* __restrict__ mask,    // (N, O, I, K)
    const int*   __restrict__ shifts,  // (N, K)
    float*       __restrict__ out)     // (O, N)
{
    __shared__ float Wsh[WSIZE];
    __shared__ float gsh[IK];

    const int tid  = threadIdx.x;
    const int warp = tid >> 5;   // warp == o; warps 0..12 also do the gather
    const int lane = tid & 31;

    // Load W once per block
    #pragma unroll
    for (int e = tid; e < WSIZE; e += THREADS)
        Wsh[e] = W[e];
    __syncthreads();

    const float bias = b[warp];
    const float e_const = 2.718281828459045f;
    const float scale = (2.0f + 2.0f * e_const) / (e_const - 1.0f);

    for (int n = blockIdx.x; n < N_DIM; n += BLOCKS) {
        // Gather: warp k (k<13) loads shift s (broadcast) + one 128B xT row,
        // stores transposed into gsh (lane*13+k: 13 coprime 32 -> conflict-free)
        if (warp < K_DIM) {
            const int s = shifts[n * K_DIM + warp];     // broadcast load
            const float gv = xT[s * I_DIM + lane];      // one coalesced line
            gsh[lane * K_DIM + warp] = gv;
        }
        __syncthreads();

        // Dot: 13 coalesced scalar mask LDGs per warp (R1-proven pattern)
        const float* __restrict__ mrow = mask + ((size_t)n * O_DIM + warp) * IK;
        const float* __restrict__ wrow = Wsh + warp * IK;

        float sum = 0.0f;
        #pragma unroll
        for (int j = 0; j < K_DIM; ++j) {
            const int e = j * 32 + lane;     // 13*32 == 416 exactly
            sum += mrow[e] * wrow[e] * gsh[e];
        }

        // Warp reduction
        #pragma unroll
        for (int off = 16; off > 0; off >>= 1)
            sum += __shfl_xor_sync(0xffffffffu, sum, off);

        if (lane == 0) {
            const float y   = sum + bias;
            const float sig = 1.0f / (1.0f + __expf(-y));
            out[warp * N_DIM + n] = (sig - 0.5f) * scale;
        }
        __syncthreads();   // protect gsh before next iteration overwrites it
    }
}

extern "C" void kernel_launch(void* const* d_in, const int* in_sizes, int n_in,
                              void* d_out, int out_size) {
    const float* x      = (const float*)d_in[0];
    const float* Wconv  = (const float*)d_in[1];
    const float* bconv  = (const float*)d_in[2];
    const float* mask   = (const float*)d_in[3];
    const int*   shifts = (const int*)d_in[4];
    float* out          = (float*)d_out;

    dim3 tb(32, 32);
    transpose_kernel<<<N_DIM / 32, tb>>>(x);
    plaq_kernel<<<BLOCKS, THREADS>>>(Wconv, bconv, mask, shifts, out);
}

// round 9
// speedup vs baseline: 1.3202x; 1.0801x over previous
#include <cuda_runtime.h>
#include <math.h>

// Problem constants
#define O_DIM 32
#define I_DIM 32
#define K_DIM 13
#define N_DIM 4096
#define IK    (I_DIM * K_DIM)    // 416
#define WSIZE (O_DIM * IK)       // 13312 floats = 53 KB

#define THREADS 1024
#define BLOCKS  304              // 152 SMs * 2 resident blocks (all co-resident)

// Transposed x: xT[n][i] = x[i][n]  (4096 x 32 floats = 512 KB, L2-resident)
__device__ float xT[N_DIM * I_DIM];
// Grid-barrier epoch counter (monotonic across graph replays)
__device__ unsigned int g_bar;

__global__ void __launch_bounds__(THREADS, 2) plaq_kernel(
    const float* __restrict__ x,       // (I, N)
    const float* __restrict__ W,       // (O, I, K)
    const float* __restrict__ b,       // (O,)
    const float* __restrict__ mask,    // (N, O, I, K)
    const int*   __restrict__ shifts,  // (N, K)
    float*       __restrict__ out)     // (O, N)
{
    __shared__ float Wsh[WSIZE];
    __shared__ float gsh[2][IK];

    const int tid  = threadIdx.x;
    const int warp = tid >> 5;   // warp == o in the dot phase
    const int lane = tid & 31;
    const int bid  = blockIdx.x;

    // ---- Phase 1: in-kernel transpose (blocks 0..127, one 32x32 tile each).
    // Tile buffer aliases the head of Wsh (Wsh is written only after this phase).
    {
        float (*tile)[33] = (float(*)[33])Wsh;
        if (bid < N_DIM / 32) {
            const int n0t = bid * 32;
            const int tx = lane, ty = warp;
            tile[ty][tx] = x[ty * N_DIM + n0t + tx];
            __syncthreads();
            xT[(n0t + ty) * I_DIM + tx] = tile[tx][ty];
            __threadfence();               // publish xT before arriving
        }
        __syncthreads();                   // tile reads done before Wsh overwrite
    }

    // ---- Phase 2: load W into shared (overlaps other blocks' transpose work)
    #pragma unroll
    for (int e = tid; e < WSIZE; e += THREADS)
        Wsh[e] = W[e];
    __syncthreads();

    // ---- Phase 3: software grid barrier (replay-safe epoch arithmetic)
    if (tid == 0) {
        const unsigned old    = atomicAdd(&g_bar, 1u);
        const unsigned target = (old / BLOCKS + 1u) * BLOCKS;
        while (atomicAdd(&g_bar, 0u) < target)
            __nanosleep(64);
    }
    __syncthreads();

    const float bias = b[warp];
    const float e_const = 2.718281828459045f;
    const float scale = (2.0f + 2.0f * e_const) / (e_const - 1.0f);
    const float* __restrict__ wrow = Wsh + warp * IK;

    // ---- Phase 4: main loop, two n's per iteration
    for (int n0 = 2 * bid; n0 < N_DIM; n0 += 2 * BLOCKS) {
        // Gather both n's: warp k (k<13) -> n0, warp 13+k -> n0+1.
        // One broadcast shift + one 128B xT row per warp; STS lane*13+k is
        // conflict-free (13 coprime with 32).
        if (warp < 2 * K_DIM) {
            const int which = (warp >= K_DIM) ? 1 : 0;
            const int k     = warp - which * K_DIM;
            const int s     = shifts[(n0 + which) * K_DIM + k];
            gsh[which][lane * K_DIM + k] = xT[s * I_DIM + lane];
        }
        __syncthreads();

        // Dot: 26 coalesced scalar mask LDGs per warp (13 per n)
        const float* __restrict__ m0 = mask + ((size_t)n0 * O_DIM + warp) * IK;
        const float* __restrict__ m1 = m0 + O_DIM * IK;

        float s0 = 0.0f, s1 = 0.0f;
        #pragma unroll
        for (int j = 0; j < K_DIM; ++j) {
            const int e = j * 32 + lane;     // 13*32 == 416 exactly
            const float w = wrow[e];
            s0 += m0[e] * w * gsh[0][e];
            s1 += m1[e] * w * gsh[1][e];
        }

        // Warp reductions
        #pragma unroll
        for (int off = 16; off > 0; off >>= 1) {
            s0 += __shfl_xor_sync(0xffffffffu, s0, off);
            s1 += __shfl_xor_sync(0xffffffffu, s1, off);
        }

        if (lane == 0) {
            const float y0 = s0 + bias;
            const float y1 = s1 + bias;
            out[warp * N_DIM + n0]     = (1.0f / (1.0f + __expf(-y0)) - 0.5f) * scale;
            out[warp * N_DIM + n0 + 1] = (1.0f / (1.0f + __expf(-y1)) - 0.5f) * scale;
        }
        __syncthreads();   // protect gsh before next iteration overwrites it
    }
}

extern "C" void kernel_launch(void* const* d_in, const int* in_sizes, int n_in,
                              void* d_out, int out_size) {
    const float* x      = (const float*)d_in[0];
    const float* Wconv  = (const float*)d_in[1];
    const float* bconv  = (const float*)d_in[2];
    const float* mask   = (const float*)d_in[3];
    const int*   shifts = (const int*)d_in[4];
    float* out          = (float*)d_out;

    plaq_kernel<<<BLOCKS, THREADS>>>(x, Wconv, bconv, mask, shifts, out);
}